// round 4
// baseline (speedup 1.0000x reference)
#include <cuda_runtime.h>
#include <cuda_bf16.h>
#include <cstdint>

// Problem constants: N=100000 nodes, D=128, E=1600000 edges.
#define MAX_N 100000
#define MAX_E 2000000
#define DD 128
#define BN_EPS 1e-5f

// Scratch (static __device__ — no allocations allowed)
__device__ __align__(16) float g_agg[MAX_N * DD];     // mean-aggregated features
__device__ __align__(16) float g_hr[MAX_N * DD];      // h_r = x @ W_r^T
__device__ int   g_degi[MAX_N];
__device__ int   g_rowstart[MAX_N + 1];
__device__ int   g_cursor[MAX_N];
__device__ int   g_csr[MAX_E];
__device__ int   g_bsum[256];
__device__ int   g_boff[256];
__device__ __align__(16) float g_colsum[DD];
__device__ __align__(16) float g_colsumsq[DD];
__device__ __align__(16) float g_scale[DD];
__device__ __align__(16) float g_shift[DD];
__device__ int g_idx64;

// ---------------------------------------------------------------------------
// 1. zero degree hist + detect edge_index dtype
__global__ void init_kernel(const int* __restrict__ ei32, int N) {
    int i = blockIdx.x * blockDim.x + threadIdx.x;
    if (i < N) g_degi[i] = 0;
    if (i == 0) {
        int ok = 1;
#pragma unroll
        for (int k = 0; k < 64; k++) ok &= (ei32[2 * k + 1] == 0);
        g_idx64 = ok;
    }
}

// 2. degree histogram over dst
__global__ void hist_kernel(const void* __restrict__ ei_raw, int E) {
    int e = blockIdx.x * blockDim.x + threadIdx.x;
    if (e >= E) return;
    int dst;
    if (g_idx64) dst = (int)((const long long*)ei_raw)[E + e];
    else         dst = ((const int*)ei_raw)[E + e];
    atomicAdd(&g_degi[dst], 1);
}

// 3. scan pass 1
__global__ void scan_p1_kernel(int N) {
    __shared__ int wsum[8];
    const int t = threadIdx.x;
    const int lane = t & 31, w = t >> 5;
    const int base = blockIdx.x * 1024 + t * 4;

    int v0 = 0, v1 = 0, v2 = 0, v3 = 0;
    if (base + 0 < N) v0 = g_degi[base + 0];
    if (base + 1 < N) v1 = g_degi[base + 1];
    if (base + 2 < N) v2 = g_degi[base + 2];
    if (base + 3 < N) v3 = g_degi[base + 3];
    const int s = v0 + v1 + v2 + v3;

    int incl = s;
#pragma unroll
    for (int o = 1; o < 32; o <<= 1) {
        int n = __shfl_up_sync(0xFFFFFFFFu, incl, o);
        if (lane >= o) incl += n;
    }
    if (lane == 31) wsum[w] = incl;
    __syncthreads();
    if (w == 0) {
        int ws = (lane < 8) ? wsum[lane] : 0;
#pragma unroll
        for (int o = 1; o < 8; o <<= 1) {
            int n = __shfl_up_sync(0xFFFFFFFFu, ws, o);
            if (lane >= o) ws += n;
        }
        if (lane < 8) wsum[lane] = ws;
    }
    __syncthreads();
    const int woff = (w > 0) ? wsum[w - 1] : 0;
    const int te = woff + incl - s;
    if (base + 0 < N) g_rowstart[base + 0] = te;
    if (base + 1 < N) g_rowstart[base + 1] = te + v0;
    if (base + 2 < N) g_rowstart[base + 2] = te + v0 + v1;
    if (base + 3 < N) g_rowstart[base + 3] = te + v0 + v1 + v2;
    if (t == 255) g_bsum[blockIdx.x] = woff + incl;
}

// 4. scan pass 2 (block totals) + zero BN stats
__global__ void scan_p2_kernel(int nb) {
    __shared__ int ws2[4];
    const int t = threadIdx.x;        // 128 threads
    const int lane = t & 31, w = t >> 5;
    int v = (t < nb) ? g_bsum[t] : 0;
    int incl = v;
#pragma unroll
    for (int o = 1; o < 32; o <<= 1) {
        int n = __shfl_up_sync(0xFFFFFFFFu, incl, o);
        if (lane >= o) incl += n;
    }
    if (lane == 31) ws2[w] = incl;
    __syncthreads();
    if (w == 0 && lane < 4) {
        int x = ws2[lane];
#pragma unroll
        for (int o = 1; o < 4; o <<= 1) {
            int n = __shfl_up_sync(0x0000000Fu, x, o);
            if (lane >= o) x += n;
        }
        ws2[lane] = x;
    }
    __syncthreads();
    incl += (w > 0) ? ws2[w - 1] : 0;
    g_boff[t] = incl - v;
    g_colsum[t] = 0.f;
    g_colsumsq[t] = 0.f;
}

// 5. scan pass 3
__global__ void scan_p3_kernel(int N, int E) {
    int i = blockIdx.x * blockDim.x + threadIdx.x;
    if (i < N) {
        int r = g_rowstart[i] + g_boff[i >> 10];
        g_rowstart[i] = r;
        g_cursor[i] = r;
    }
    if (i == 0) g_rowstart[N] = E;
}

// 6. CSR fill
__global__ void fill_kernel(const void* __restrict__ ei_raw, int E) {
    int e = blockIdx.x * blockDim.x + threadIdx.x;
    if (e >= E) return;
    int src, dst;
    if (g_idx64) {
        const long long* p = (const long long*)ei_raw;
        src = (int)p[e]; dst = (int)p[E + e];
    } else {
        const int* p = (const int*)ei_raw;
        src = p[e]; dst = p[E + e];
    }
    int pos = atomicAdd(&g_cursor[dst], 1);
    g_csr[pos] = src;
}

// ---------------------------------------------------------------------------
// Shared 128x128x128 fp32 GEMM core: C[128x128] = A[128 rows x 128] * W^T
// (W is [128 x 128] row-major; B[k][j] = W[j][k]). 256 threads, 8x8/thread.
__device__ __forceinline__ void gemm128_core(
    const float* __restrict__ A, const float* __restrict__ W,
    int rowBase, int N, float (&c)[8][8],
    float (*As)[136], float (*Bs)[136]) {

    const int tid = threadIdx.x;
    const int tx = tid & 15;
    const int ty = tid >> 4;
    const int lm = tid >> 1;
    const int lk = (tid & 1) * 8;

#pragma unroll
    for (int i = 0; i < 8; i++)
#pragma unroll
        for (int j = 0; j < 8; j++) c[i][j] = 0.f;

    for (int kt = 0; kt < 8; kt++) {
        const int kofs = kt * 16;
        {
            int row = rowBase + lm;
            float4 f0 = make_float4(0, 0, 0, 0), f1 = f0;
            if (row < N) {
                const float* base = A + (size_t)row * DD + kofs + lk;
                f0 = reinterpret_cast<const float4*>(base)[0];
                f1 = reinterpret_cast<const float4*>(base)[1];
            }
            As[lk + 0][lm] = f0.x; As[lk + 1][lm] = f0.y;
            As[lk + 2][lm] = f0.z; As[lk + 3][lm] = f0.w;
            As[lk + 4][lm] = f1.x; As[lk + 5][lm] = f1.y;
            As[lk + 6][lm] = f1.z; As[lk + 7][lm] = f1.w;
        }
        {
            const float* base = W + (size_t)lm * DD + kofs + lk;
            float4 f0 = reinterpret_cast<const float4*>(base)[0];
            float4 f1 = reinterpret_cast<const float4*>(base)[1];
            Bs[lk + 0][lm] = f0.x; Bs[lk + 1][lm] = f0.y;
            Bs[lk + 2][lm] = f0.z; Bs[lk + 3][lm] = f0.w;
            Bs[lk + 4][lm] = f1.x; Bs[lk + 5][lm] = f1.y;
            Bs[lk + 6][lm] = f1.z; Bs[lk + 7][lm] = f1.w;
        }
        __syncthreads();

#pragma unroll
        for (int k = 0; k < 16; k++) {
            float a[8], b[8];
#pragma unroll
            for (int i = 0; i < 8; i++) a[i] = As[k][ty * 8 + i];
#pragma unroll
            for (int j = 0; j < 8; j++) b[j] = Bs[k][tx * 8 + j];
#pragma unroll
            for (int i = 0; i < 8; i++)
#pragma unroll
                for (int j = 0; j < 8; j++) c[i][j] = fmaf(a[i], b[j], c[i][j]);
        }
        __syncthreads();
    }
}

// ---------------------------------------------------------------------------
// 7. FUSED kernel: blocks [0, G2) compute h_r = x @ W_r^T -> g_hr (FFMA-bound),
//    blocks [G2, ...) gather-aggregate the mean (L2-bound). They overlap.
__global__ __launch_bounds__(256, 2)
void fused_gather_gemmr(const float* __restrict__ x,
                        const float* __restrict__ W_r,
                        int N, int G2) {
    __shared__ float As[16][136];
    __shared__ float Bs[16][136];

    if (blockIdx.x < G2) {
        // ---- GEMM: h_r = x @ W_r^T ----
        const int rowBase = blockIdx.x * 128;
        float c[8][8];
        gemm128_core(x, W_r, rowBase, N, c, As, Bs);

        const int tx = threadIdx.x & 15;
        const int ty = threadIdx.x >> 4;
#pragma unroll
        for (int i = 0; i < 8; i++) {
            int row = rowBase + ty * 8 + i;
            if (row < N) {
                float4 o0 = make_float4(c[i][0], c[i][1], c[i][2], c[i][3]);
                float4 o1 = make_float4(c[i][4], c[i][5], c[i][6], c[i][7]);
                float4* dst = reinterpret_cast<float4*>(g_hr + (size_t)row * DD + tx * 8);
                dst[0] = o0; dst[1] = o1;
            }
        }
    } else {
        // ---- gather-aggregate: one warp per node ----
        const int warp = ((blockIdx.x - G2) * blockDim.x + threadIdx.x) >> 5;
        const int lane = threadIdx.x & 31;
        if (warp >= N) return;

        const int start = g_rowstart[warp];
        const int end   = g_rowstart[warp + 1];

        float4 acc0 = make_float4(0.f, 0.f, 0.f, 0.f);
        float4 acc1 = make_float4(0.f, 0.f, 0.f, 0.f);
        for (int eb = start; eb < end; eb += 32) {
            int n = end - eb; if (n > 32) n = 32;
            int myid = (lane < n) ? g_csr[eb + lane] : 0;
            int j = 0;
            for (; j + 2 <= n; j += 2) {
                int s0 = __shfl_sync(0xFFFFFFFFu, myid, j);
                int s1 = __shfl_sync(0xFFFFFFFFu, myid, j + 1);
                float4 v0 = reinterpret_cast<const float4*>(x + (size_t)s0 * DD)[lane];
                float4 v1 = reinterpret_cast<const float4*>(x + (size_t)s1 * DD)[lane];
                acc0.x += v0.x; acc0.y += v0.y; acc0.z += v0.z; acc0.w += v0.w;
                acc1.x += v1.x; acc1.y += v1.y; acc1.z += v1.z; acc1.w += v1.w;
            }
            if (j < n) {
                int s0 = __shfl_sync(0xFFFFFFFFu, myid, j);
                float4 v0 = reinterpret_cast<const float4*>(x + (size_t)s0 * DD)[lane];
                acc0.x += v0.x; acc0.y += v0.y; acc0.z += v0.z; acc0.w += v0.w;
            }
        }
        const float inv = 1.0f / fmaxf((float)(end - start), 1.0f);
        float4 o = make_float4((acc0.x + acc1.x) * inv, (acc0.y + acc1.y) * inv,
                               (acc0.z + acc1.z) * inv, (acc0.w + acc1.w) * inv);
        reinterpret_cast<float4*>(g_agg + (size_t)warp * DD)[lane] = o;
    }
}

// ---------------------------------------------------------------------------
// 8. gemm_l: h = agg @ W_l^T + h_r + b_l ; relu ; store ; BN stats
__global__ __launch_bounds__(256, 2)
void gemm_l_bn_kernel(const float* __restrict__ W_l,
                      const float* __restrict__ b_l,
                      float* __restrict__ out,
                      int N) {
    __shared__ float As[16][136];
    __shared__ float Bs[16][136];

    const int rowBase = blockIdx.x * 128;
    float c[8][8];
    gemm128_core(g_agg, W_l, rowBase, N, c, As, Bs);

    const int tx = threadIdx.x & 15;
    const int ty = threadIdx.x >> 4;

    float bias[8];
#pragma unroll
    for (int j = 0; j < 8; j++) bias[j] = b_l[tx * 8 + j];

    float psum[8], psq[8];
#pragma unroll
    for (int j = 0; j < 8; j++) { psum[j] = 0.f; psq[j] = 0.f; }

#pragma unroll
    for (int i = 0; i < 8; i++) {
        int row = rowBase + ty * 8 + i;
        if (row < N) {
            const float4* hr = reinterpret_cast<const float4*>(g_hr + (size_t)row * DD + tx * 8);
            float4 r0 = hr[0], r1 = hr[1];
            float4 o0, o1;
            float v;
            v = fmaxf(c[i][0] + r0.x + bias[0], 0.f); o0.x = v; psum[0] += v; psq[0] += v * v;
            v = fmaxf(c[i][1] + r0.y + bias[1], 0.f); o0.y = v; psum[1] += v; psq[1] += v * v;
            v = fmaxf(c[i][2] + r0.z + bias[2], 0.f); o0.z = v; psum[2] += v; psq[2] += v * v;
            v = fmaxf(c[i][3] + r0.w + bias[3], 0.f); o0.w = v; psum[3] += v; psq[3] += v * v;
            v = fmaxf(c[i][4] + r1.x + bias[4], 0.f); o1.x = v; psum[4] += v; psq[4] += v * v;
            v = fmaxf(c[i][5] + r1.y + bias[5], 0.f); o1.y = v; psum[5] += v; psq[5] += v * v;
            v = fmaxf(c[i][6] + r1.z + bias[6], 0.f); o1.z = v; psum[6] += v; psq[6] += v * v;
            v = fmaxf(c[i][7] + r1.w + bias[7], 0.f); o1.w = v; psum[7] += v; psq[7] += v * v;
            float4* dst = reinterpret_cast<float4*>(out + (size_t)row * DD + tx * 8);
            dst[0] = o0; dst[1] = o1;
        }
    }

#pragma unroll
    for (int j = 0; j < 8; j++) {
        As[ty][tx * 8 + j] = psum[j];
        Bs[ty][tx * 8 + j] = psq[j];
    }
    __syncthreads();
    if (ty == 0) {
#pragma unroll
        for (int j = 0; j < 8; j++) {
            int col = tx * 8 + j;
            float s = 0.f;
#pragma unroll
            for (int r = 0; r < 16; r++) s += As[r][col];
            atomicAdd(&g_colsum[col], s);
        }
    } else if (ty == 1) {
#pragma unroll
        for (int j = 0; j < 8; j++) {
            int col = tx * 8 + j;
            float s = 0.f;
#pragma unroll
            for (int r = 0; r < 16; r++) s += Bs[r][col];
            atomicAdd(&g_colsumsq[col], s);
        }
    }
}

// ---------------------------------------------------------------------------
__global__ void bn_prep_kernel(const float* __restrict__ gamma,
                               const float* __restrict__ beta,
                               float invN) {
    int j = threadIdx.x;
    if (j < DD) {
        float mu = g_colsum[j] * invN;
        float var = fmaxf(g_colsumsq[j] * invN - mu * mu, 0.f);
        float rs = rsqrtf(var + BN_EPS);
        float sc = gamma[j] * rs;
        g_scale[j] = sc;
        g_shift[j] = beta[j] - mu * sc;
    }
}

__global__ void bn_apply_kernel(float* __restrict__ out, int n4) {
    int i = blockIdx.x * blockDim.x + threadIdx.x;
    if (i >= n4) return;
    int j = (i & 31) * 4;
    float4 v = reinterpret_cast<float4*>(out)[i];
    v.x = v.x * g_scale[j + 0] + g_shift[j + 0];
    v.y = v.y * g_scale[j + 1] + g_shift[j + 1];
    v.z = v.z * g_scale[j + 2] + g_shift[j + 2];
    v.w = v.w * g_scale[j + 3] + g_shift[j + 3];
    reinterpret_cast<float4*>(out)[i] = v;
}

// ---------------------------------------------------------------------------
extern "C" void kernel_launch(void* const* d_in, const int* in_sizes, int n_in,
                              void* d_out, int out_size) {
    const float* x     = (const float*)d_in[0];
    const void*  ei    = d_in[1];
    const float* W_l   = (const float*)d_in[2];
    const float* b_l   = (const float*)d_in[3];
    const float* W_r   = (const float*)d_in[4];
    const float* gamma = (const float*)d_in[5];
    const float* beta  = (const float*)d_in[6];
    float* out         = (float*)d_out;

    const int N = in_sizes[0] / DD;    // 100000
    const int E = in_sizes[1] / 2;     // 1600000
    const int nScanBlocks = (N + 1023) / 1024;
    const int G2 = (N + 127) / 128;            // gemm blocks
    const int G1 = (N + 7) / 8;                // gather blocks (8 warps each)

    init_kernel<<<(N + 255) / 256, 256>>>((const int*)ei, N);
    hist_kernel<<<(E + 255) / 256, 256>>>(ei, E);
    scan_p1_kernel<<<nScanBlocks, 256>>>(N);
    scan_p2_kernel<<<1, 128>>>(nScanBlocks);
    scan_p3_kernel<<<(N + 255) / 256, 256>>>(N, E);
    fill_kernel<<<(E + 255) / 256, 256>>>(ei, E);
    // fused: gemm_r (blocks [0,G2)) overlapped with gather (blocks [G2, G2+G1))
    fused_gather_gemmr<<<G2 + G1, 256>>>(x, W_r, N, G2);
    gemm_l_bn_kernel<<<G2, 256>>>(W_l, b_l, out, N);
    bn_prep_kernel<<<1, 128>>>(gamma, beta, 1.0f / (float)N);
    bn_apply_kernel<<<(N * (DD / 4) + 255) / 256, 256>>>(out, N * (DD / 4));
}

// round 5
// speedup vs baseline: 1.2841x; 1.2841x over previous
#include <cuda_runtime.h>
#include <cuda_fp16.h>
#include <cstdint>

// Problem constants: N=100000 nodes, D=128, E=1600000 edges.
#define MAX_N 100000
#define MAX_E 2000000
#define DD 128
#define BN_EPS 1e-5f

// Scratch (static __device__ — no allocations allowed)
__device__ __align__(16) float  g_agg[MAX_N * DD];   // mean-aggregated features
__device__ __align__(16) __half g_xh[MAX_N * DD];    // fp16 mirror of x (gather input)
__device__ int   g_degi[MAX_N];
__device__ int   g_rowstart[MAX_N + 1];
__device__ int   g_cursor[MAX_N];
__device__ int   g_csr[MAX_E];
__device__ int   g_bsum[256];
__device__ int   g_boff[256];
__device__ __align__(16) float g_colsum[DD];
__device__ __align__(16) float g_colsumsq[DD];
__device__ __align__(16) float g_scale[DD];
__device__ __align__(16) float g_shift[DD];
__device__ int g_idx64;

// ---------------------------------------------------------------------------
// 1. zero degree hist + detect edge_index dtype (int64 => high words all 0)
__global__ void init_kernel(const int* __restrict__ ei32, int N) {
    int i = blockIdx.x * blockDim.x + threadIdx.x;
    if (i < N) g_degi[i] = 0;
    if (i == 0) {
        int ok = 1;
#pragma unroll
        for (int k = 0; k < 64; k++) ok &= (ei32[2 * k + 1] == 0);
        g_idx64 = ok;
    }
}

// 1b. fp16 mirror of x: each thread converts 8 floats -> 8 halves (one uint4)
__global__ void convert_kernel(const float* __restrict__ x, int total8) {
    int i = blockIdx.x * blockDim.x + threadIdx.x;
    if (i >= total8) return;
    float4 a = reinterpret_cast<const float4*>(x)[2 * i];
    float4 b = reinterpret_cast<const float4*>(x)[2 * i + 1];
    __half2 h0 = __floats2half2_rn(a.x, a.y);
    __half2 h1 = __floats2half2_rn(a.z, a.w);
    __half2 h2 = __floats2half2_rn(b.x, b.y);
    __half2 h3 = __floats2half2_rn(b.z, b.w);
    uint4 o;
    o.x = *reinterpret_cast<uint32_t*>(&h0);
    o.y = *reinterpret_cast<uint32_t*>(&h1);
    o.z = *reinterpret_cast<uint32_t*>(&h2);
    o.w = *reinterpret_cast<uint32_t*>(&h3);
    reinterpret_cast<uint4*>(g_xh)[i] = o;
}

// 2. degree histogram over dst
__global__ void hist_kernel(const void* __restrict__ ei_raw, int E) {
    int e = blockIdx.x * blockDim.x + threadIdx.x;
    if (e >= E) return;
    int dst;
    if (g_idx64) dst = (int)((const long long*)ei_raw)[E + e];
    else         dst = ((const int*)ei_raw)[E + e];
    atomicAdd(&g_degi[dst], 1);
}

// 3. scan pass 1
__global__ void scan_p1_kernel(int N) {
    __shared__ int wsum[8];
    const int t = threadIdx.x;
    const int lane = t & 31, w = t >> 5;
    const int base = blockIdx.x * 1024 + t * 4;

    int v0 = 0, v1 = 0, v2 = 0, v3 = 0;
    if (base + 0 < N) v0 = g_degi[base + 0];
    if (base + 1 < N) v1 = g_degi[base + 1];
    if (base + 2 < N) v2 = g_degi[base + 2];
    if (base + 3 < N) v3 = g_degi[base + 3];
    const int s = v0 + v1 + v2 + v3;

    int incl = s;
#pragma unroll
    for (int o = 1; o < 32; o <<= 1) {
        int n = __shfl_up_sync(0xFFFFFFFFu, incl, o);
        if (lane >= o) incl += n;
    }
    if (lane == 31) wsum[w] = incl;
    __syncthreads();
    if (w == 0) {
        int ws = (lane < 8) ? wsum[lane] : 0;
#pragma unroll
        for (int o = 1; o < 8; o <<= 1) {
            int n = __shfl_up_sync(0xFFFFFFFFu, ws, o);
            if (lane >= o) ws += n;
        }
        if (lane < 8) wsum[lane] = ws;
    }
    __syncthreads();
    const int woff = (w > 0) ? wsum[w - 1] : 0;
    const int te = woff + incl - s;
    if (base + 0 < N) g_rowstart[base + 0] = te;
    if (base + 1 < N) g_rowstart[base + 1] = te + v0;
    if (base + 2 < N) g_rowstart[base + 2] = te + v0 + v1;
    if (base + 3 < N) g_rowstart[base + 3] = te + v0 + v1 + v2;
    if (t == 255) g_bsum[blockIdx.x] = woff + incl;
}

// 4. scan pass 2 (block totals) + zero BN stats
__global__ void scan_p2_kernel(int nb) {
    __shared__ int ws2[4];
    const int t = threadIdx.x;        // 128 threads
    const int lane = t & 31, w = t >> 5;
    int v = (t < nb) ? g_bsum[t] : 0;
    int incl = v;
#pragma unroll
    for (int o = 1; o < 32; o <<= 1) {
        int n = __shfl_up_sync(0xFFFFFFFFu, incl, o);
        if (lane >= o) incl += n;
    }
    if (lane == 31) ws2[w] = incl;
    __syncthreads();
    if (w == 0 && lane < 4) {
        int x = ws2[lane];
#pragma unroll
        for (int o = 1; o < 4; o <<= 1) {
            int n = __shfl_up_sync(0x0000000Fu, x, o);
            if (lane >= o) x += n;
        }
        ws2[lane] = x;
    }
    __syncthreads();
    incl += (w > 0) ? ws2[w - 1] : 0;
    g_boff[t] = incl - v;
    g_colsum[t] = 0.f;
    g_colsumsq[t] = 0.f;
}

// 5. scan pass 3
__global__ void scan_p3_kernel(int N, int E) {
    int i = blockIdx.x * blockDim.x + threadIdx.x;
    if (i < N) {
        int r = g_rowstart[i] + g_boff[i >> 10];
        g_rowstart[i] = r;
        g_cursor[i] = r;
    }
    if (i == 0) g_rowstart[N] = E;
}

// 6. CSR fill
__global__ void fill_kernel(const void* __restrict__ ei_raw, int E) {
    int e = blockIdx.x * blockDim.x + threadIdx.x;
    if (e >= E) return;
    int src, dst;
    if (g_idx64) {
        const long long* p = (const long long*)ei_raw;
        src = (int)p[e]; dst = (int)p[E + e];
    } else {
        const int* p = (const int*)ei_raw;
        src = p[e]; dst = p[E + e];
    }
    int pos = atomicAdd(&g_cursor[dst], 1);
    g_csr[pos] = src;
}

// ---------------------------------------------------------------------------
// 7. Gather-aggregate over fp16 mirror. One warp per node; lanes 0-15 process
// even neighbors, lanes 16-31 odd neighbors (two rows in flight per step).
// Each lane loads uint4 = 8 halves (row is 256B = 16 lanes x 16B).
__device__ __forceinline__ void accum8(float* acc, uint4 v) {
    float2 f;
    f = __half22float2(*reinterpret_cast<__half2*>(&v.x)); acc[0] += f.x; acc[1] += f.y;
    f = __half22float2(*reinterpret_cast<__half2*>(&v.y)); acc[2] += f.x; acc[3] += f.y;
    f = __half22float2(*reinterpret_cast<__half2*>(&v.z)); acc[4] += f.x; acc[5] += f.y;
    f = __half22float2(*reinterpret_cast<__half2*>(&v.w)); acc[6] += f.x; acc[7] += f.y;
}

__global__ __launch_bounds__(256)
void gather_kernel(int N) {
    const int warp = (blockIdx.x * blockDim.x + threadIdx.x) >> 5;
    const int lane = threadIdx.x & 31;
    if (warp >= N) return;
    const int half_id = lane >> 4;
    const int sub = lane & 15;

    const int start = g_rowstart[warp];
    const int end   = g_rowstart[warp + 1];

    float acc[8];
#pragma unroll
    for (int k = 0; k < 8; k++) acc[k] = 0.f;

    const uint4* xh = reinterpret_cast<const uint4*>(g_xh);  // 16 uint4 per row

    for (int eb = start; eb < end; eb += 32) {
        int n = end - eb; if (n > 32) n = 32;
        int myid = (lane < n) ? g_csr[eb + lane] : 0;
        int j = 0;
        // 4 neighbors per iteration (2 per half-warp, MLP=2)
        for (; j + 4 <= n; j += 4) {
            int s0 = __shfl_sync(0xFFFFFFFFu, myid, j + half_id);
            int s1 = __shfl_sync(0xFFFFFFFFu, myid, j + 2 + half_id);
            uint4 v0 = xh[(size_t)s0 * 16 + sub];
            uint4 v1 = xh[(size_t)s1 * 16 + sub];
            accum8(acc, v0);
            accum8(acc, v1);
        }
        // tail (up to 3 neighbors)
        for (; j < n; j += 2) {
            bool hasB = (j + 1 < n);
            int idx = hasB ? (j + half_id) : j;
            int s = __shfl_sync(0xFFFFFFFFu, myid, idx);
            uint4 v = xh[(size_t)s * 16 + sub];
            if (half_id == 0 || hasB) accum8(acc, v);
        }
    }

    // combine the two half-warps (same columns)
#pragma unroll
    for (int k = 0; k < 8; k++) acc[k] += __shfl_xor_sync(0xFFFFFFFFu, acc[k], 16);

    if (half_id == 0) {
        const float inv = 1.0f / fmaxf((float)(end - start), 1.0f);
        float4 o0 = make_float4(acc[0] * inv, acc[1] * inv, acc[2] * inv, acc[3] * inv);
        float4 o1 = make_float4(acc[4] * inv, acc[5] * inv, acc[6] * inv, acc[7] * inv);
        float4* dst = reinterpret_cast<float4*>(g_agg + (size_t)warp * DD + sub * 8);
        dst[0] = o0; dst[1] = o1;
    }
}

// ---------------------------------------------------------------------------
// 8. Fused double-buffered GEMM: h = agg @ W_l^T + b_l + x @ W_r^T ; relu ;
// store h ; BN column stats. A[N x 256] (agg | x), B[256 x 128] (W_l^T; W_r^T).
// BM=128, BN=128, BK=16, 16 K-tiles; 256 threads, 8x8 per thread; 2-stage smem.
__global__ __launch_bounds__(256, 2)
void gemm_bn_kernel(const float* __restrict__ x,
                    const float* __restrict__ W_l,
                    const float* __restrict__ b_l,
                    const float* __restrict__ W_r,
                    float* __restrict__ out,
                    int N) {
    __shared__ float As[2][16][136];
    __shared__ float Bs[2][16][136];

    const int tid = threadIdx.x;
    const int tx = tid & 15;
    const int ty = tid >> 4;
    const int rowBase = blockIdx.x * 128;
    const int lm = tid >> 1;
    const int lk = (tid & 1) * 8;

    float c[8][8];
#pragma unroll
    for (int i = 0; i < 8; i++)
#pragma unroll
        for (int j = 0; j < 8; j++) c[i][j] = 0.f;

    // --- prologue: load tile 0 directly into stage 0 ---
    {
        int row = rowBase + lm;
        float4 f0 = make_float4(0, 0, 0, 0), f1 = f0;
        if (row < N) {
            const float* base = g_agg + (size_t)row * DD + lk;
            f0 = reinterpret_cast<const float4*>(base)[0];
            f1 = reinterpret_cast<const float4*>(base)[1];
        }
        As[0][lk + 0][lm] = f0.x; As[0][lk + 1][lm] = f0.y;
        As[0][lk + 2][lm] = f0.z; As[0][lk + 3][lm] = f0.w;
        As[0][lk + 4][lm] = f1.x; As[0][lk + 5][lm] = f1.y;
        As[0][lk + 6][lm] = f1.z; As[0][lk + 7][lm] = f1.w;

        const float* wb = W_l + (size_t)lm * DD + lk;
        float4 g0 = reinterpret_cast<const float4*>(wb)[0];
        float4 g1 = reinterpret_cast<const float4*>(wb)[1];
        Bs[0][lk + 0][lm] = g0.x; Bs[0][lk + 1][lm] = g0.y;
        Bs[0][lk + 2][lm] = g0.z; Bs[0][lk + 3][lm] = g0.w;
        Bs[0][lk + 4][lm] = g1.x; Bs[0][lk + 5][lm] = g1.y;
        Bs[0][lk + 6][lm] = g1.z; Bs[0][lk + 7][lm] = g1.w;
    }
    __syncthreads();

    for (int kt = 0; kt < 16; kt++) {
        const int cur = kt & 1;
        float4 na0, na1, nb0, nb1;
        if (kt < 15) {
            const int k2 = kt + 1;
            const bool isAgg = (k2 < 8);
            const int kofs = (k2 & 7) * 16;
            int row = rowBase + lm;
            na0 = make_float4(0, 0, 0, 0); na1 = na0;
            if (row < N) {
                const float* base = (isAgg ? g_agg : x) + (size_t)row * DD + kofs + lk;
                na0 = reinterpret_cast<const float4*>(base)[0];
                na1 = reinterpret_cast<const float4*>(base)[1];
            }
            const float* wb = (isAgg ? W_l : W_r) + (size_t)lm * DD + kofs + lk;
            nb0 = reinterpret_cast<const float4*>(wb)[0];
            nb1 = reinterpret_cast<const float4*>(wb)[1];
        }

        // compute on stage cur
#pragma unroll
        for (int k = 0; k < 16; k++) {
            float a[8], b[8];
#pragma unroll
            for (int i = 0; i < 8; i++) a[i] = As[cur][k][ty * 8 + i];
#pragma unroll
            for (int j = 0; j < 8; j++) b[j] = Bs[cur][k][tx * 8 + j];
#pragma unroll
            for (int i = 0; i < 8; i++)
#pragma unroll
                for (int j = 0; j < 8; j++) c[i][j] = fmaf(a[i], b[j], c[i][j]);
        }

        if (kt < 15) {
            const int nxt = cur ^ 1;
            As[nxt][lk + 0][lm] = na0.x; As[nxt][lk + 1][lm] = na0.y;
            As[nxt][lk + 2][lm] = na0.z; As[nxt][lk + 3][lm] = na0.w;
            As[nxt][lk + 4][lm] = na1.x; As[nxt][lk + 5][lm] = na1.y;
            As[nxt][lk + 6][lm] = na1.z; As[nxt][lk + 7][lm] = na1.w;
            Bs[nxt][lk + 0][lm] = nb0.x; Bs[nxt][lk + 1][lm] = nb0.y;
            Bs[nxt][lk + 2][lm] = nb0.z; Bs[nxt][lk + 3][lm] = nb0.w;
            Bs[nxt][lk + 4][lm] = nb1.x; Bs[nxt][lk + 5][lm] = nb1.y;
            Bs[nxt][lk + 6][lm] = nb1.z; Bs[nxt][lk + 7][lm] = nb1.w;
            __syncthreads();
        }
    }

    // --- epilogue: +bias, relu, store, BN stats ---
    float bias[8];
#pragma unroll
    for (int j = 0; j < 8; j++) bias[j] = b_l[tx * 8 + j];

    float psum[8], psq[8];
#pragma unroll
    for (int j = 0; j < 8; j++) { psum[j] = 0.f; psq[j] = 0.f; }

#pragma unroll
    for (int i = 0; i < 8; i++) {
        int row = rowBase + ty * 8 + i;
        if (row < N) {
            float4 o0, o1;
            float v;
            v = fmaxf(c[i][0] + bias[0], 0.f); o0.x = v; psum[0] += v; psq[0] += v * v;
            v = fmaxf(c[i][1] + bias[1], 0.f); o0.y = v; psum[1] += v; psq[1] += v * v;
            v = fmaxf(c[i][2] + bias[2], 0.f); o0.z = v; psum[2] += v; psq[2] += v * v;
            v = fmaxf(c[i][3] + bias[3], 0.f); o0.w = v; psum[3] += v; psq[3] += v * v;
            v = fmaxf(c[i][4] + bias[4], 0.f); o1.x = v; psum[4] += v; psq[4] += v * v;
            v = fmaxf(c[i][5] + bias[5], 0.f); o1.y = v; psum[5] += v; psq[5] += v * v;
            v = fmaxf(c[i][6] + bias[6], 0.f); o1.z = v; psum[6] += v; psq[6] += v * v;
            v = fmaxf(c[i][7] + bias[7], 0.f); o1.w = v; psum[7] += v; psq[7] += v * v;
            float4* dst = reinterpret_cast<float4*>(out + (size_t)row * DD + tx * 8);
            dst[0] = o0; dst[1] = o1;
        }
    }

    __syncthreads();  // done reading smem for compute; reuse stage 0 as scratch
#pragma unroll
    for (int j = 0; j < 8; j++) {
        As[0][ty][tx * 8 + j] = psum[j];
        Bs[0][ty][tx * 8 + j] = psq[j];
    }
    __syncthreads();
    if (ty == 0) {
#pragma unroll
        for (int j = 0; j < 8; j++) {
            int col = tx * 8 + j;
            float s = 0.f;
#pragma unroll
            for (int r = 0; r < 16; r++) s += As[0][r][col];
            atomicAdd(&g_colsum[col], s);
        }
    } else if (ty == 1) {
#pragma unroll
        for (int j = 0; j < 8; j++) {
            int col = tx * 8 + j;
            float s = 0.f;
#pragma unroll
            for (int r = 0; r < 16; r++) s += Bs[0][r][col];
            atomicAdd(&g_colsumsq[col], s);
        }
    }
}

// ---------------------------------------------------------------------------
__global__ void bn_prep_kernel(const float* __restrict__ gamma,
                               const float* __restrict__ beta,
                               float invN) {
    int j = threadIdx.x;
    if (j < DD) {
        float mu = g_colsum[j] * invN;
        float var = fmaxf(g_colsumsq[j] * invN - mu * mu, 0.f);
        float rs = rsqrtf(var + BN_EPS);
        float sc = gamma[j] * rs;
        g_scale[j] = sc;
        g_shift[j] = beta[j] - mu * sc;
    }
}

__global__ void bn_apply_kernel(float* __restrict__ out, int n4) {
    int i = blockIdx.x * blockDim.x + threadIdx.x;
    if (i >= n4) return;
    int j = (i & 31) * 4;
    float4 v = reinterpret_cast<float4*>(out)[i];
    v.x = v.x * g_scale[j + 0] + g_shift[j + 0];
    v.y = v.y * g_scale[j + 1] + g_shift[j + 1];
    v.z = v.z * g_scale[j + 2] + g_shift[j + 2];
    v.w = v.w * g_scale[j + 3] + g_shift[j + 3];
    reinterpret_cast<float4*>(out)[i] = v;
}

// ---------------------------------------------------------------------------
extern "C" void kernel_launch(void* const* d_in, const int* in_sizes, int n_in,
                              void* d_out, int out_size) {
    const float* x     = (const float*)d_in[0];
    const void*  ei    = d_in[1];
    const float* W_l   = (const float*)d_in[2];
    const float* b_l   = (const float*)d_in[3];
    const float* W_r   = (const float*)d_in[4];
    const float* gamma = (const float*)d_in[5];
    const float* beta  = (const float*)d_in[6];
    float* out         = (float*)d_out;

    const int N = in_sizes[0] / DD;    // 100000
    const int E = in_sizes[1] / 2;     // 1600000
    const int nScanBlocks = (N + 1023) / 1024;

    init_kernel<<<(N + 255) / 256, 256>>>((const int*)ei, N);
    convert_kernel<<<(N * DD / 8 + 255) / 256, 256>>>(x, N * DD / 8);
    hist_kernel<<<(E + 255) / 256, 256>>>(ei, E);
    scan_p1_kernel<<<nScanBlocks, 256>>>(N);
    scan_p2_kernel<<<1, 128>>>(nScanBlocks);
    scan_p3_kernel<<<(N + 255) / 256, 256>>>(N, E);
    fill_kernel<<<(E + 255) / 256, 256>>>(ei, E);
    gather_kernel<<<(N + 7) / 8, 256>>>(N);
    gemm_bn_kernel<<<(N + 127) / 128, 256>>>(x, W_l, b_l, W_r, out, N);
    bn_prep_kernel<<<1, 128>>>(gamma, beta, 1.0f / (float)N);
    bn_apply_kernel<<<(N * (DD / 4) + 255) / 256, 256>>>(out, N * (DD / 4));
}

// round 6
// speedup vs baseline: 2.4016x; 1.8703x over previous
#include <cuda_runtime.h>
#include <cuda_fp16.h>
#include <cstdint>

// Problem constants: N=100000 nodes, D=128, E=1600000 edges.
#define MAX_N 100000
#define MAX_E 2000000
#define DD 128
#define BN_EPS 1e-5f

// Scratch (static __device__ — no allocations allowed)
__device__ __align__(16) __half g_xh[MAX_N * DD];    // fp16 mirror of x
__device__ __align__(16) __half g_aggh[MAX_N * DD];  // fp16 mean-aggregated feats
__device__ __align__(16) __half g_wlh[DD * DD];      // fp16 W_l
__device__ __align__(16) __half g_wrh[DD * DD];      // fp16 W_r
__device__ int   g_degi[MAX_N];
__device__ int   g_rowstart[MAX_N + 1];
__device__ int   g_cursor[MAX_N];
__device__ int   g_csr[MAX_E];
__device__ int   g_bsum[256];
__device__ int   g_boff[256];
__device__ __align__(16) float g_colsum[DD];
__device__ __align__(16) float g_colsumsq[DD];
__device__ __align__(16) float g_scale[DD];
__device__ __align__(16) float g_shift[DD];
__device__ int g_idx64;

// ---------------------------------------------------------------------------
// 1. zero degree hist + detect edge_index dtype (int64 => high words all 0)
__global__ void init_kernel(const int* __restrict__ ei32, int N) {
    int i = blockIdx.x * blockDim.x + threadIdx.x;
    if (i < N) g_degi[i] = 0;
    if (i == 0) {
        int ok = 1;
#pragma unroll
        for (int k = 0; k < 64; k++) ok &= (ei32[2 * k + 1] == 0);
        g_idx64 = ok;
    }
}

// 1b. fp16 mirrors: x (n8x groups of 8 floats), then W_l (2048), then W_r (2048)
__global__ void convert_kernel(const float* __restrict__ x,
                               const float* __restrict__ W_l,
                               const float* __restrict__ W_r,
                               int n8x) {
    int i = blockIdx.x * blockDim.x + threadIdx.x;
    const float* src;
    __half* dst;
    int idx;
    if (i < n8x) { src = x; dst = g_xh; idx = i; }
    else if (i < n8x + 2048) { src = W_l; dst = g_wlh; idx = i - n8x; }
    else if (i < n8x + 4096) { src = W_r; dst = g_wrh; idx = i - n8x - 2048; }
    else return;
    float4 a = reinterpret_cast<const float4*>(src)[2 * idx];
    float4 b = reinterpret_cast<const float4*>(src)[2 * idx + 1];
    __half2 h0 = __floats2half2_rn(a.x, a.y);
    __half2 h1 = __floats2half2_rn(a.z, a.w);
    __half2 h2 = __floats2half2_rn(b.x, b.y);
    __half2 h3 = __floats2half2_rn(b.z, b.w);
    uint4 o;
    o.x = *reinterpret_cast<uint32_t*>(&h0);
    o.y = *reinterpret_cast<uint32_t*>(&h1);
    o.z = *reinterpret_cast<uint32_t*>(&h2);
    o.w = *reinterpret_cast<uint32_t*>(&h3);
    reinterpret_cast<uint4*>(dst)[idx] = o;
}

// 2. degree histogram over dst
__global__ void hist_kernel(const void* __restrict__ ei_raw, int E) {
    int e = blockIdx.x * blockDim.x + threadIdx.x;
    if (e >= E) return;
    int dst;
    if (g_idx64) dst = (int)((const long long*)ei_raw)[E + e];
    else         dst = ((const int*)ei_raw)[E + e];
    atomicAdd(&g_degi[dst], 1);
}

// 3. scan pass 1
__global__ void scan_p1_kernel(int N) {
    __shared__ int wsum[8];
    const int t = threadIdx.x;
    const int lane = t & 31, w = t >> 5;
    const int base = blockIdx.x * 1024 + t * 4;

    int v0 = 0, v1 = 0, v2 = 0, v3 = 0;
    if (base + 0 < N) v0 = g_degi[base + 0];
    if (base + 1 < N) v1 = g_degi[base + 1];
    if (base + 2 < N) v2 = g_degi[base + 2];
    if (base + 3 < N) v3 = g_degi[base + 3];
    const int s = v0 + v1 + v2 + v3;

    int incl = s;
#pragma unroll
    for (int o = 1; o < 32; o <<= 1) {
        int n = __shfl_up_sync(0xFFFFFFFFu, incl, o);
        if (lane >= o) incl += n;
    }
    if (lane == 31) wsum[w] = incl;
    __syncthreads();
    if (w == 0) {
        int ws = (lane < 8) ? wsum[lane] : 0;
#pragma unroll
        for (int o = 1; o < 8; o <<= 1) {
            int n = __shfl_up_sync(0xFFFFFFFFu, ws, o);
            if (lane >= o) ws += n;
        }
        if (lane < 8) wsum[lane] = ws;
    }
    __syncthreads();
    const int woff = (w > 0) ? wsum[w - 1] : 0;
    const int te = woff + incl - s;
    if (base + 0 < N) g_rowstart[base + 0] = te;
    if (base + 1 < N) g_rowstart[base + 1] = te + v0;
    if (base + 2 < N) g_rowstart[base + 2] = te + v0 + v1;
    if (base + 3 < N) g_rowstart[base + 3] = te + v0 + v1 + v2;
    if (t == 255) g_bsum[blockIdx.x] = woff + incl;
}

// 4. scan pass 2 (block totals) + zero BN stats
__global__ void scan_p2_kernel(int nb) {
    __shared__ int ws2[4];
    const int t = threadIdx.x;        // 128 threads
    const int lane = t & 31, w = t >> 5;
    int v = (t < nb) ? g_bsum[t] : 0;
    int incl = v;
#pragma unroll
    for (int o = 1; o < 32; o <<= 1) {
        int n = __shfl_up_sync(0xFFFFFFFFu, incl, o);
        if (lane >= o) incl += n;
    }
    if (lane == 31) ws2[w] = incl;
    __syncthreads();
    if (w == 0 && lane < 4) {
        int x = ws2[lane];
#pragma unroll
        for (int o = 1; o < 4; o <<= 1) {
            int n = __shfl_up_sync(0x0000000Fu, x, o);
            if (lane >= o) x += n;
        }
        ws2[lane] = x;
    }
    __syncthreads();
    incl += (w > 0) ? ws2[w - 1] : 0;
    g_boff[t] = incl - v;
    g_colsum[t] = 0.f;
    g_colsumsq[t] = 0.f;
}

// 5. scan pass 3
__global__ void scan_p3_kernel(int N, int E) {
    int i = blockIdx.x * blockDim.x + threadIdx.x;
    if (i < N) {
        int r = g_rowstart[i] + g_boff[i >> 10];
        g_rowstart[i] = r;
        g_cursor[i] = r;
    }
    if (i == 0) g_rowstart[N] = E;
}

// 6. CSR fill
__global__ void fill_kernel(const void* __restrict__ ei_raw, int E) {
    int e = blockIdx.x * blockDim.x + threadIdx.x;
    if (e >= E) return;
    int src, dst;
    if (g_idx64) {
        const long long* p = (const long long*)ei_raw;
        src = (int)p[e]; dst = (int)p[E + e];
    } else {
        const int* p = (const int*)ei_raw;
        src = p[e]; dst = p[E + e];
    }
    int pos = atomicAdd(&g_cursor[dst], 1);
    g_csr[pos] = src;
}

// ---------------------------------------------------------------------------
// 7. Gather-aggregate over fp16 mirror; writes fp16 mean rows (g_aggh).
__device__ __forceinline__ void accum8(float* acc, uint4 v) {
    float2 f;
    f = __half22float2(*reinterpret_cast<__half2*>(&v.x)); acc[0] += f.x; acc[1] += f.y;
    f = __half22float2(*reinterpret_cast<__half2*>(&v.y)); acc[2] += f.x; acc[3] += f.y;
    f = __half22float2(*reinterpret_cast<__half2*>(&v.z)); acc[4] += f.x; acc[5] += f.y;
    f = __half22float2(*reinterpret_cast<__half2*>(&v.w)); acc[6] += f.x; acc[7] += f.y;
}

__global__ __launch_bounds__(256)
void gather_kernel(int N) {
    const int warp = (blockIdx.x * blockDim.x + threadIdx.x) >> 5;
    const int lane = threadIdx.x & 31;
    if (warp >= N) return;
    const int half_id = lane >> 4;
    const int sub = lane & 15;

    const int start = g_rowstart[warp];
    const int end   = g_rowstart[warp + 1];

    float acc[8];
#pragma unroll
    for (int k = 0; k < 8; k++) acc[k] = 0.f;

    const uint4* xh = reinterpret_cast<const uint4*>(g_xh);  // 16 uint4 per row

    for (int eb = start; eb < end; eb += 32) {
        int n = end - eb; if (n > 32) n = 32;
        int myid = (lane < n) ? g_csr[eb + lane] : 0;
        int j = 0;
        for (; j + 4 <= n; j += 4) {
            int s0 = __shfl_sync(0xFFFFFFFFu, myid, j + half_id);
            int s1 = __shfl_sync(0xFFFFFFFFu, myid, j + 2 + half_id);
            uint4 v0 = xh[(size_t)s0 * 16 + sub];
            uint4 v1 = xh[(size_t)s1 * 16 + sub];
            accum8(acc, v0);
            accum8(acc, v1);
        }
        for (; j < n; j += 2) {
            bool hasB = (j + 1 < n);
            int idx = hasB ? (j + half_id) : j;
            int s = __shfl_sync(0xFFFFFFFFu, myid, idx);
            uint4 v = xh[(size_t)s * 16 + sub];
            if (half_id == 0 || hasB) accum8(acc, v);
        }
    }

#pragma unroll
    for (int k = 0; k < 8; k++) acc[k] += __shfl_xor_sync(0xFFFFFFFFu, acc[k], 16);

    if (half_id == 0) {
        const float inv = 1.0f / fmaxf((float)(end - start), 1.0f);
        __half2 h0 = __floats2half2_rn(acc[0] * inv, acc[1] * inv);
        __half2 h1 = __floats2half2_rn(acc[2] * inv, acc[3] * inv);
        __half2 h2 = __floats2half2_rn(acc[4] * inv, acc[5] * inv);
        __half2 h3 = __floats2half2_rn(acc[6] * inv, acc[7] * inv);
        uint4 o;
        o.x = *reinterpret_cast<uint32_t*>(&h0);
        o.y = *reinterpret_cast<uint32_t*>(&h1);
        o.z = *reinterpret_cast<uint32_t*>(&h2);
        o.w = *reinterpret_cast<uint32_t*>(&h3);
        reinterpret_cast<uint4*>(g_aggh + (size_t)warp * DD)[sub] = o;
    }
}

// ---------------------------------------------------------------------------
// 8. HMMA GEMM: h = [aggh | xh] (Nx256 fp16) @ [W_l^T; W_r^T] + b_l ; relu ;
// store fp32 h to out. mma.sync m16n8k16 fp16->fp32.
// Block: 128x128 output, 256 threads (8 warps in 4x2: warp_m=wid&3, warp_n=wid>>2).
// Warp tile 32x64 = 2 m-tiles x 8 n-tiles. K loop: 8 tiles of BK=32.
// smem rows padded to 40 halves (80B) -> conflict-free ldmatrix.
__global__ __launch_bounds__(256, 2)
void gemm_hmma_kernel(const float* __restrict__ b_l,
                      float* __restrict__ out,
                      int N) {
    __shared__ __align__(16) __half sA[128 * 40];
    __shared__ __align__(16) __half sB[128 * 40];

    const int tid = threadIdx.x;
    const int lane = tid & 31;
    const int wid = tid >> 5;
    const int warp_m = wid & 3;
    const int warp_n = wid >> 2;
    const int rowBase = blockIdx.x * 128;

    float d[2][8][4];
#pragma unroll
    for (int mt = 0; mt < 2; mt++)
#pragma unroll
        for (int nt = 0; nt < 8; nt++)
#pragma unroll
            for (int r = 0; r < 4; r++) d[mt][nt][r] = 0.f;

    const int lr = tid >> 1;          // 0..127: row in tile
    const int lc = (tid & 1) * 16;    // 0 or 16: half-offset within 32

    for (int kt = 0; kt < 8; kt++) {
        // --- load A (128x32) and B (128x32) tiles ---
        {
            const __half* srcA = (kt < 4) ? g_aggh : g_xh;
            int row = rowBase + lr;
            uint4 v0 = make_uint4(0, 0, 0, 0), v1 = v0;
            if (row < N) {
                const uint4* p = reinterpret_cast<const uint4*>(
                    srcA + (size_t)row * DD + (kt & 3) * 32 + lc);
                v0 = p[0]; v1 = p[1];
            }
            *reinterpret_cast<uint4*>(&sA[lr * 40 + lc]) = v0;
            *reinterpret_cast<uint4*>(&sA[lr * 40 + lc + 8]) = v1;

            const __half* srcB = (kt < 4) ? g_wlh : g_wrh;
            const uint4* q = reinterpret_cast<const uint4*>(
                srcB + (size_t)lr * DD + (kt & 3) * 32 + lc);
            uint4 w0 = q[0], w1 = q[1];
            *reinterpret_cast<uint4*>(&sB[lr * 40 + lc]) = w0;
            *reinterpret_cast<uint4*>(&sB[lr * 40 + lc + 8]) = w1;
        }
        __syncthreads();

#pragma unroll
        for (int ks = 0; ks < 32; ks += 16) {
            uint32_t a[2][4];
#pragma unroll
            for (int mt = 0; mt < 2; mt++) {
                int arow = warp_m * 32 + mt * 16 + (lane & 15);
                int akk = ks + ((lane >> 4) << 3);
                uint32_t addr = (uint32_t)__cvta_generic_to_shared(&sA[arow * 40 + akk]);
                asm volatile(
                    "ldmatrix.sync.aligned.m8n8.x4.shared.b16 {%0,%1,%2,%3}, [%4];"
                    : "=r"(a[mt][0]), "=r"(a[mt][1]), "=r"(a[mt][2]), "=r"(a[mt][3])
                    : "r"(addr));
            }
            uint32_t b[8][2];
#pragma unroll
            for (int nt = 0; nt < 8; nt++) {
                int brow = warp_n * 64 + nt * 8 + (lane & 7);
                int bkk = ks + ((lane & 8) ? 8 : 0);
                uint32_t addr = (uint32_t)__cvta_generic_to_shared(&sB[brow * 40 + bkk]);
                asm volatile(
                    "ldmatrix.sync.aligned.m8n8.x2.shared.b16 {%0,%1}, [%2];"
                    : "=r"(b[nt][0]), "=r"(b[nt][1])
                    : "r"(addr));
            }
#pragma unroll
            for (int mt = 0; mt < 2; mt++)
#pragma unroll
                for (int nt = 0; nt < 8; nt++) {
                    asm volatile(
                        "mma.sync.aligned.m16n8k16.row.col.f32.f16.f16.f32 "
                        "{%0,%1,%2,%3}, {%4,%5,%6,%7}, {%8,%9}, {%0,%1,%2,%3};"
                        : "+f"(d[mt][nt][0]), "+f"(d[mt][nt][1]),
                          "+f"(d[mt][nt][2]), "+f"(d[mt][nt][3])
                        : "r"(a[mt][0]), "r"(a[mt][1]), "r"(a[mt][2]), "r"(a[mt][3]),
                          "r"(b[nt][0]), "r"(b[nt][1]));
                }
        }
        __syncthreads();
    }

    // --- epilogue: +bias, relu, store fp32 h ---
#pragma unroll
    for (int nt = 0; nt < 8; nt++) {
        int col = warp_n * 64 + nt * 8 + ((lane & 3) << 1);
        float b0 = __ldg(&b_l[col]);
        float b1 = __ldg(&b_l[col + 1]);
#pragma unroll
        for (int mt = 0; mt < 2; mt++) {
            int row = rowBase + warp_m * 32 + mt * 16 + (lane >> 2);
            if (row < N) {
                float2 v = make_float2(fmaxf(d[mt][nt][0] + b0, 0.f),
                                       fmaxf(d[mt][nt][1] + b1, 0.f));
                *reinterpret_cast<float2*>(out + (size_t)row * DD + col) = v;
            }
            if (row + 8 < N) {
                float2 v = make_float2(fmaxf(d[mt][nt][2] + b0, 0.f),
                                       fmaxf(d[mt][nt][3] + b1, 0.f));
                *reinterpret_cast<float2*>(out + (size_t)(row + 8) * DD + col) = v;
            }
        }
    }
}

// ---------------------------------------------------------------------------
// 9. BN column stats over out (h). One block per 128 rows.
__global__ __launch_bounds__(256)
void bn_stats_kernel(const float* __restrict__ out, int N) {
    __shared__ float ss[256], qq[256];
    const int tid = threadIdx.x;
    const int col = tid & 127;
    const int h = tid >> 7;
    const int rowBase = blockIdx.x * 128;

    float s = 0.f, q = 0.f;
    for (int r = h; r < 128; r += 2) {
        int row = rowBase + r;
        if (row < N) {
            float v = out[(size_t)row * DD + col];
            s += v; q += v * v;
        }
    }
    ss[tid] = s; qq[tid] = q;
    __syncthreads();
    if (h == 0) {
        atomicAdd(&g_colsum[col], ss[tid] + ss[tid + 128]);
        atomicAdd(&g_colsumsq[col], qq[tid] + qq[tid + 128]);
    }
}

// ---------------------------------------------------------------------------
__global__ void bn_prep_kernel(const float* __restrict__ gamma,
                               const float* __restrict__ beta,
                               float invN) {
    int j = threadIdx.x;
    if (j < DD) {
        float mu = g_colsum[j] * invN;
        float var = fmaxf(g_colsumsq[j] * invN - mu * mu, 0.f);
        float rs = rsqrtf(var + BN_EPS);
        float sc = gamma[j] * rs;
        g_scale[j] = sc;
        g_shift[j] = beta[j] - mu * sc;
    }
}

__global__ void bn_apply_kernel(float* __restrict__ out, int n4) {
    int i = blockIdx.x * blockDim.x + threadIdx.x;
    if (i >= n4) return;
    int j = (i & 31) * 4;
    float4 v = reinterpret_cast<float4*>(out)[i];
    v.x = v.x * g_scale[j + 0] + g_shift[j + 0];
    v.y = v.y * g_scale[j + 1] + g_shift[j + 1];
    v.z = v.z * g_scale[j + 2] + g_shift[j + 2];
    v.w = v.w * g_scale[j + 3] + g_shift[j + 3];
    reinterpret_cast<float4*>(out)[i] = v;
}

// ---------------------------------------------------------------------------
extern "C" void kernel_launch(void* const* d_in, const int* in_sizes, int n_in,
                              void* d_out, int out_size) {
    const float* x     = (const float*)d_in[0];
    const void*  ei    = d_in[1];
    const float* W_l   = (const float*)d_in[2];
    const float* b_l   = (const float*)d_in[3];
    const float* W_r   = (const float*)d_in[4];
    const float* gamma = (const float*)d_in[5];
    const float* beta  = (const float*)d_in[6];
    float* out         = (float*)d_out;

    const int N = in_sizes[0] / DD;    // 100000
    const int E = in_sizes[1] / 2;     // 1600000
    const int nScanBlocks = (N + 1023) / 1024;
    const int n8x = N * DD / 8;

    init_kernel<<<(N + 255) / 256, 256>>>((const int*)ei, N);
    convert_kernel<<<(n8x + 4096 + 255) / 256, 256>>>(x, W_l, W_r, n8x);
    hist_kernel<<<(E + 255) / 256, 256>>>(ei, E);
    scan_p1_kernel<<<nScanBlocks, 256>>>(N);
    scan_p2_kernel<<<1, 128>>>(nScanBlocks);
    scan_p3_kernel<<<(N + 255) / 256, 256>>>(N, E);
    fill_kernel<<<(E + 255) / 256, 256>>>(ei, E);
    gather_kernel<<<(N + 7) / 8, 256>>>(N);
    gemm_hmma_kernel<<<(N + 127) / 128, 256>>>(b_l, out, N);
    bn_stats_kernel<<<(N + 127) / 128, 256>>>(out, N);
    bn_prep_kernel<<<1, 128>>>(gamma, beta, 1.0f / (float)N);
    bn_apply_kernel<<<(N * (DD / 4) + 255) / 256, 256>>>(out, N * (DD / 4));
}